// round 1
// baseline (speedup 1.0000x reference)
#include <cuda_runtime.h>
#include <cuda_fp16.h>

#define SHIFTV 4
#define HEADS 4

// pitches in __half units (chosen so word-pitch % 32 == 4 -> conflict-free frags)
#define XP 136   // Xs/Os [64][128]
#define WP 136   // Wt [32][128] (transposed weight stage)
#define QP 40    // Qs/Ks [64][32]
#define VP 72    // Vt [32][64]  (V transposed)
#define PP 72    // Ps [64][64]  (softmax probs, half)
#define SP 68    // Ss [64][64]  (logits, float)

#define SMEM_HALVES (64*XP + 64*XP + 32*WP + 64*QP + 64*QP + 32*VP + 64*PP)
#define SMEM_FLOATS (64*SP + 225*HEADS + 384 + 128)
#define SMEM_BYTES  (SMEM_HALVES*2 + SMEM_FLOATS*4)

__device__ __forceinline__ void mma_f16(float& c0, float& c1, float& c2, float& c3,
                                        unsigned a0, unsigned a1, unsigned a2, unsigned a3,
                                        unsigned b0, unsigned b1) {
    asm volatile(
        "mma.sync.aligned.m16n8k16.row.col.f32.f16.f16.f32 "
        "{%0,%1,%2,%3},{%4,%5,%6,%7},{%8,%9},{%0,%1,%2,%3};\n"
        : "+f"(c0), "+f"(c1), "+f"(c2), "+f"(c3)
        : "r"(a0), "r"(a1), "r"(a2), "r"(a3), "r"(b0), "r"(b1));
}

__device__ __forceinline__ unsigned ld_h2(const __half* p) {
    return *reinterpret_cast<const unsigned*>(p);
}

__device__ __forceinline__ float bias_at(const float* Bs, int h, int i, int j) {
    int idx = ((i >> 3) - (j >> 3) + 7) * 15 + ((i & 7) - (j & 7) + 7);
    return Bs[idx * HEADS + h];
}

__global__ __launch_bounds__(256) void swin_win_attn_kernel(
    const float* __restrict__ x, const float* __restrict__ qkv_w,
    const float* __restrict__ qkv_b, const float* __restrict__ proj_w,
    const float* __restrict__ proj_b, const float* __restrict__ bias_table,
    float* __restrict__ out)
{
    extern __shared__ char smem_raw[];
    __half* Xs = reinterpret_cast<__half*>(smem_raw);   // window input (fp16)
    __half* Os = Xs + 64 * XP;                          // attention output (fp16)
    __half* Wt = Os + 64 * XP;                          // staged weight slice, transposed [n][k]
    __half* Qs = Wt + 32 * WP;
    __half* Ks = Qs + 64 * QP;
    __half* Vt = Ks + 64 * QP;                          // V transposed [d][m]
    __half* Ps = Vt + 32 * VP;                          // probs (fp16)
    float*  Ss = reinterpret_cast<float*>(Ps + 64 * PP);// logits (fp32)
    float*  Bs = Ss + 64 * SP;                          // bias table
    float*  qb = Bs + 225 * HEADS;                      // qkv_b
    float*  pb = qb + 384;                              // proj_b

    const int tid = threadIdx.x, lane = tid & 31, wid = tid >> 5;
    const int g = lane >> 2, tg = lane & 3;

    const int widx = blockIdx.x;
    const int b = widx >> 12, wh = (widx >> 6) & 63, ww = widx & 63;

    // ---- gather window (roll by -SHIFT folded into index) ----
    #pragma unroll
    for (int it = tid; it < 64 * 32; it += 256) {
        int t = it >> 5, c4 = (it & 31) * 4;
        int i = t >> 3, j = t & 7;
        int gr = (wh * 8 + i + SHIFTV) & 511;
        int gc = (ww * 8 + j + SHIFTV) & 511;
        float4 v = *reinterpret_cast<const float4*>(
            x + (((size_t)b * 512 + gr) * 512 + gc) * 128 + c4);
        __half2* dst = reinterpret_cast<__half2*>(Xs + t * XP + c4);
        dst[0] = __floats2half2_rn(v.x, v.y);
        dst[1] = __floats2half2_rn(v.z, v.w);
    }
    for (int i = tid; i < 225 * HEADS; i += 256) Bs[i] = bias_table[i];
    for (int i = tid; i < 384; i += 256) qb[i] = qkv_b[i];
    if (tid < 128) pb[tid] = proj_b[tid];
    __syncthreads();

    // stage a [128][32] weight slice transposed into Wt[n][k]
    auto stage_w = [&](const float* w, int ld, int colbase) {
        for (int it = tid; it < 128 * 32; it += 256) {
            int k = it >> 5, n = it & 31;
            Wt[n * WP + k] = __float2half_rn(w[k * ld + colbase + n]);
        }
    };

    // C[64x32] = Xs[64x128] @ Wt^T + bias ; store normal or transposed
    auto qkv_gemm = [&](const float* bias_base, __half* dst, int dpitch, bool trans) {
        const int mt = wid >> 1, nb = (wid & 1) * 2;
        float c[2][4] = {};
        const __half* Abase = Xs + (mt * 16 + g) * XP + 2 * tg;
        #pragma unroll
        for (int ks = 0; ks < 8; ++ks) {
            int k0 = ks * 16;
            unsigned a0 = ld_h2(Abase + k0);
            unsigned a1 = ld_h2(Abase + 8 * XP + k0);
            unsigned a2 = ld_h2(Abase + k0 + 8);
            unsigned a3 = ld_h2(Abase + 8 * XP + k0 + 8);
            #pragma unroll
            for (int p = 0; p < 2; ++p) {
                const __half* Bb = Wt + ((nb + p) * 8 + g) * WP + 2 * tg + k0;
                mma_f16(c[p][0], c[p][1], c[p][2], c[p][3],
                        a0, a1, a2, a3, ld_h2(Bb), ld_h2(Bb + 8));
            }
        }
        const int row = mt * 16 + g;
        #pragma unroll
        for (int p = 0; p < 2; ++p) {
            int col = (nb + p) * 8 + 2 * tg;
            float b0 = bias_base[col], b1 = bias_base[col + 1];
            if (!trans) {
                *reinterpret_cast<__half2*>(dst + row * dpitch + col) =
                    __floats2half2_rn(c[p][0] + b0, c[p][1] + b1);
                *reinterpret_cast<__half2*>(dst + (row + 8) * dpitch + col) =
                    __floats2half2_rn(c[p][2] + b0, c[p][3] + b1);
            } else {
                dst[col * dpitch + row]           = __float2half_rn(c[p][0] + b0);
                dst[(col + 1) * dpitch + row]     = __float2half_rn(c[p][1] + b1);
                dst[col * dpitch + row + 8]       = __float2half_rn(c[p][2] + b0);
                dst[(col + 1) * dpitch + row + 8] = __float2half_rn(c[p][3] + b1);
            }
        }
    };

    const float scale = 0.17677669529663687f;  // 32^-0.5

    for (int h = 0; h < HEADS; ++h) {
        // ---- Q, K, V for this head ----
        stage_w(qkv_w, 384, h * 32);
        __syncthreads();
        qkv_gemm(qb + h * 32, Qs, QP, false);
        __syncthreads();
        stage_w(qkv_w, 384, 128 + h * 32);
        __syncthreads();
        qkv_gemm(qb + 128 + h * 32, Ks, QP, false);
        __syncthreads();
        stage_w(qkv_w, 384, 256 + h * 32);
        __syncthreads();
        qkv_gemm(qb + 256 + h * 32, Vt, VP, true);
        __syncthreads();

        // ---- S = Q K^T * scale + bias ----
        {
            const int mt = wid >> 1, nb = (wid & 1) * 4;
            float c[4][4] = {};
            const __half* Abase = Qs + (mt * 16 + g) * QP + 2 * tg;
            #pragma unroll
            for (int ks = 0; ks < 2; ++ks) {
                int k0 = ks * 16;
                unsigned a0 = ld_h2(Abase + k0);
                unsigned a1 = ld_h2(Abase + 8 * QP + k0);
                unsigned a2 = ld_h2(Abase + k0 + 8);
                unsigned a3 = ld_h2(Abase + 8 * QP + k0 + 8);
                #pragma unroll
                for (int p = 0; p < 4; ++p) {
                    const __half* Bb = Ks + ((nb + p) * 8 + g) * QP + 2 * tg + k0;
                    mma_f16(c[p][0], c[p][1], c[p][2], c[p][3],
                            a0, a1, a2, a3, ld_h2(Bb), ld_h2(Bb + 8));
                }
            }
            const int row = mt * 16 + g;
            #pragma unroll
            for (int p = 0; p < 4; ++p) {
                int col = (nb + p) * 8 + 2 * tg;
                Ss[row * SP + col]           = c[p][0] * scale + bias_at(Bs, h, row, col);
                Ss[row * SP + col + 1]       = c[p][1] * scale + bias_at(Bs, h, row, col + 1);
                Ss[(row + 8) * SP + col]     = c[p][2] * scale + bias_at(Bs, h, row + 8, col);
                Ss[(row + 8) * SP + col + 1] = c[p][3] * scale + bias_at(Bs, h, row + 8, col + 1);
            }
        }
        __syncthreads();

        // ---- softmax (4 threads per row, exact fp32) ----
        {
            const int row = tid >> 2, sub = tid & 3;
            float v[16];
            float m = -1e30f;
            #pragma unroll
            for (int i = 0; i < 16; ++i) {
                v[i] = Ss[row * SP + sub + 4 * i];
                m = fmaxf(m, v[i]);
            }
            m = fmaxf(m, __shfl_xor_sync(0xffffffffu, m, 1));
            m = fmaxf(m, __shfl_xor_sync(0xffffffffu, m, 2));
            float s = 0.f;
            #pragma unroll
            for (int i = 0; i < 16; ++i) { v[i] = __expf(v[i] - m); s += v[i]; }
            s += __shfl_xor_sync(0xffffffffu, s, 1);
            s += __shfl_xor_sync(0xffffffffu, s, 2);
            float inv = 1.0f / s;
            #pragma unroll
            for (int i = 0; i < 16; ++i)
                Ps[row * PP + sub + 4 * i] = __float2half_rn(v[i] * inv);
        }
        __syncthreads();

        // ---- O[:, h*32:] = P @ V ----
        {
            const int mt = wid >> 1, nb = (wid & 1) * 2;
            float c[2][4] = {};
            const __half* Abase = Ps + (mt * 16 + g) * PP + 2 * tg;
            #pragma unroll
            for (int ks = 0; ks < 4; ++ks) {
                int k0 = ks * 16;
                unsigned a0 = ld_h2(Abase + k0);
                unsigned a1 = ld_h2(Abase + 8 * PP + k0);
                unsigned a2 = ld_h2(Abase + k0 + 8);
                unsigned a3 = ld_h2(Abase + 8 * PP + k0 + 8);
                #pragma unroll
                for (int p = 0; p < 2; ++p) {
                    const __half* Bb = Vt + ((nb + p) * 8 + g) * VP + 2 * tg + k0;
                    mma_f16(c[p][0], c[p][1], c[p][2], c[p][3],
                            a0, a1, a2, a3, ld_h2(Bb), ld_h2(Bb + 8));
                }
            }
            const int row = mt * 16 + g;
            #pragma unroll
            for (int p = 0; p < 2; ++p) {
                int col = h * 32 + (nb + p) * 8 + 2 * tg;
                *reinterpret_cast<__half2*>(Os + row * XP + col) =
                    __floats2half2_rn(c[p][0], c[p][1]);
                *reinterpret_cast<__half2*>(Os + (row + 8) * XP + col) =
                    __floats2half2_rn(c[p][2], c[p][3]);
            }
        }
        __syncthreads();
    }

    // ---- proj: out = O @ proj_w + proj_b, scattered write (inverse roll) ----
    for (int nc = 0; nc < 4; ++nc) {
        stage_w(proj_w, 128, nc * 32);
        __syncthreads();
        const int mt = wid >> 1, nb = (wid & 1) * 2;
        float c[2][4] = {};
        const __half* Abase = Os + (mt * 16 + g) * XP + 2 * tg;
        #pragma unroll
        for (int ks = 0; ks < 8; ++ks) {
            int k0 = ks * 16;
            unsigned a0 = ld_h2(Abase + k0);
            unsigned a1 = ld_h2(Abase + 8 * XP + k0);
            unsigned a2 = ld_h2(Abase + k0 + 8);
            unsigned a3 = ld_h2(Abase + k0 + 8 * XP + 8);
            #pragma unroll
            for (int p = 0; p < 2; ++p) {
                const __half* Bb = Wt + ((nb + p) * 8 + g) * WP + 2 * tg + k0;
                mma_f16(c[p][0], c[p][1], c[p][2], c[p][3],
                        a0, a1, a2, a3, ld_h2(Bb), ld_h2(Bb + 8));
            }
        }
        const int row = mt * 16 + g;
        #pragma unroll
        for (int p = 0; p < 2; ++p) {
            int col = nc * 32 + (nb + p) * 8 + 2 * tg;
            float b0 = pb[col], b1 = pb[col + 1];
            #pragma unroll
            for (int rr = 0; rr < 2; ++rr) {
                int t = row + rr * 8;
                int i = t >> 3, j = t & 7;
                int gr = (wh * 8 + i + SHIFTV) & 511;
                int gc = (ww * 8 + j + SHIFTV) & 511;
                float2 st;
                st.x = c[p][rr * 2 + 0] + b0;
                st.y = c[p][rr * 2 + 1] + b1;
                *reinterpret_cast<float2*>(
                    out + (((size_t)b * 512 + gr) * 512 + gc) * 128 + col) = st;
            }
        }
        __syncthreads();
    }
}

extern "C" void kernel_launch(void* const* d_in, const int* in_sizes, int n_in,
                              void* d_out, int out_size)
{
    const float* x          = (const float*)d_in[0];
    const float* qkv_w      = (const float*)d_in[1];
    const float* qkv_b      = (const float*)d_in[2];
    const float* proj_w     = (const float*)d_in[3];
    const float* proj_b     = (const float*)d_in[4];
    const float* bias_table = (const float*)d_in[5];
    float* out = (float*)d_out;

    cudaFuncSetAttribute(swin_win_attn_kernel,
                         cudaFuncAttributeMaxDynamicSharedMemorySize, SMEM_BYTES);
    swin_win_attn_kernel<<<4 * 64 * 64, 256, SMEM_BYTES>>>(
        x, qkv_w, qkv_b, proj_w, proj_b, bias_table, out);
}

// round 3
// speedup vs baseline: 1.4404x; 1.4404x over previous
#include <cuda_runtime.h>
#include <cuda_fp16.h>

#define SHIFTV 4
#define HEADS 4
#define NW 8          // windows per CTA

// pitches in __half units; word-pitch % 8 == 4 -> conflict-free frag access
#define XP 136   // Xs (input / attention-output overlay) [64][128]
#define WQP 136  // WqkvT [384][128]
#define WPP 136  // WprojT [128][128]
#define QP 40    // Qs/Ks per head [64][32]
#define VP 72    // Vt per head [32 d-rows][64 tokens] (+pad)

#define H_WQ   (384*WQP)
#define H_WP   (128*WPP)
#define H_X    (64*XP)
#define H_Q    (HEADS*64*QP)
#define H_K    (HEADS*64*QP)
#define H_V    (HEADS*32*VP)
#define SMEM_HALVES (H_WQ + H_WP + H_X + H_Q + H_K + H_V)
#define SMEM_FLOATS (225*HEADS + 384 + 128)
#define SMEM_BYTES  (SMEM_HALVES*2 + SMEM_FLOATS*4)

__device__ __align__(16) __half g_qkvT[384*128];
__device__ __align__(16) __half g_projT[128*128];

__global__ void prep_qkv(const float* __restrict__ w) {
    int i = blockIdx.x * 256 + threadIdx.x;
    if (i < 384*128) {
        int n = i >> 7, k = i & 127;
        g_qkvT[i] = __float2half_rn(w[k*384 + n]);
    }
}
__global__ void prep_proj(const float* __restrict__ w) {
    int i = blockIdx.x * 256 + threadIdx.x;
    if (i < 128*128) {
        int n = i >> 7, k = i & 127;
        g_projT[i] = __float2half_rn(w[k*128 + n]);
    }
}

__device__ __forceinline__ void mma_f16(float& c0, float& c1, float& c2, float& c3,
                                        unsigned a0, unsigned a1, unsigned a2, unsigned a3,
                                        unsigned b0, unsigned b1) {
    asm volatile(
        "mma.sync.aligned.m16n8k16.row.col.f32.f16.f16.f32 "
        "{%0,%1,%2,%3},{%4,%5,%6,%7},{%8,%9},{%0,%1,%2,%3};\n"
        : "+f"(c0), "+f"(c1), "+f"(c2), "+f"(c3)
        : "r"(a0), "r"(a1), "r"(a2), "r"(a3), "r"(b0), "r"(b1));
}

__device__ __forceinline__ unsigned ld_h2(const __half* p) {
    return *reinterpret_cast<const unsigned*>(p);
}

__device__ __forceinline__ float bias_at(const float* Bs, int h, int i, int j) {
    int idx = ((i >> 3) - (j >> 3) + 7) * 15 + ((i & 7) - (j & 7) + 7);
    return Bs[idx * HEADS + h];
}

__global__ __launch_bounds__(256, 1) void swin_win_attn_kernel(
    const float* __restrict__ x, const float* __restrict__ qkv_b,
    const float* __restrict__ proj_b, const float* __restrict__ bias_table,
    float* __restrict__ out)
{
    extern __shared__ char smem_raw[];
    __half* Wq = reinterpret_cast<__half*>(smem_raw);
    __half* Wp = Wq + H_WQ;
    __half* Xs = Wp + H_WP;      // input window; later attention output O
    __half* Qs = Xs + H_X;
    __half* Ks = Qs + H_Q;
    __half* Vt = Ks + H_K;
    float*  Bs = reinterpret_cast<float*>(Vt + H_V);
    float*  qb = Bs + 225*HEADS;
    float*  pb = qb + 384;

    const int tid = threadIdx.x, lane = tid & 31, wid = tid >> 5;
    const int g = lane >> 2, tg = lane & 3;

    // ---- one-time per CTA: resident weights (vectorized) + biases ----
    {
        const uint4* src = reinterpret_cast<const uint4*>(g_qkvT);
        for (int i = tid; i < 384*16; i += 256) {
            int r = i >> 4, c = i & 15;
            *reinterpret_cast<uint4*>(Wq + r*WQP + c*8) = src[i];
        }
        const uint4* src2 = reinterpret_cast<const uint4*>(g_projT);
        for (int i = tid; i < 128*16; i += 256) {
            int r = i >> 4, c = i & 15;
            *reinterpret_cast<uint4*>(Wp + r*WPP + c*8) = src2[i];
        }
        for (int i = tid; i < 225*HEADS; i += 256) Bs[i] = bias_table[i];
        for (int i = tid; i < 384; i += 256) qb[i] = qkv_b[i];
        if (tid < 128) pb[tid] = proj_b[tid];
    }

    const float scale = 0.17677669529663687f;  // 32^-0.5

    for (int wi = 0; wi < NW; ++wi) {
        const int widx = blockIdx.x * NW + wi;
        const int b = widx >> 12, wh = (widx >> 6) & 63, ww = widx & 63;

        __syncthreads();   // prev-window proj reads of Xs done; first iter: weight loads done

        // ---- gather window (roll folded into index), fp32 -> fp16 ----
        #pragma unroll
        for (int it = tid; it < 64*32; it += 256) {
            int t = it >> 5, c4 = (it & 31) * 4;
            int i = t >> 3, j = t & 7;
            int gr = (wh*8 + i + SHIFTV) & 511;
            int gc = (ww*8 + j + SHIFTV) & 511;
            float4 v = *reinterpret_cast<const float4*>(
                x + (((size_t)b*512 + gr)*512 + gc)*128 + c4);
            __half2* dst = reinterpret_cast<__half2*>(Xs + t*XP + c4);
            dst[0] = __floats2half2_rn(v.x, v.y);
            dst[1] = __floats2half2_rn(v.z, v.w);
        }
        __syncthreads();

        // ---- QKV: [64x128] @ [128x384]; warp owns 64 rows x 48 cols ----
        {
            const int cb = wid * 48;
            float c[4][6][4];
            #pragma unroll
            for (int mt = 0; mt < 4; ++mt)
                #pragma unroll
                for (int p = 0; p < 6; ++p)
                    c[mt][p][0] = c[mt][p][1] = c[mt][p][2] = c[mt][p][3] = 0.f;

            #pragma unroll
            for (int ks = 0; ks < 8; ++ks) {
                int k0 = ks * 16;
                unsigned a[4][4];
                #pragma unroll
                for (int mt = 0; mt < 4; ++mt) {
                    const __half* Ab = Xs + (mt*16 + g)*XP + 2*tg + k0;
                    a[mt][0] = ld_h2(Ab);
                    a[mt][1] = ld_h2(Ab + 8*XP);
                    a[mt][2] = ld_h2(Ab + 8);
                    a[mt][3] = ld_h2(Ab + 8*XP + 8);
                }
                #pragma unroll
                for (int p = 0; p < 6; ++p) {
                    const __half* Bb = Wq + (cb + p*8 + g)*WQP + 2*tg + k0;
                    unsigned b0 = ld_h2(Bb), b1 = ld_h2(Bb + 8);
                    #pragma unroll
                    for (int mt = 0; mt < 4; ++mt)
                        mma_f16(c[mt][p][0], c[mt][p][1], c[mt][p][2], c[mt][p][3],
                                a[mt][0], a[mt][1], a[mt][2], a[mt][3], b0, b1);
                }
            }
            // epilogue: route to Q / K / V(T) with bias
            #pragma unroll
            for (int p = 0; p < 6; ++p) {
                int col = cb + p*8 + 2*tg;
                int mat = col >> 7, head = (col >> 5) & 3, d = col & 31;
                float b0 = qb[col], b1 = qb[col + 1];
                #pragma unroll
                for (int mt = 0; mt < 4; ++mt) {
                    int row = mt*16 + g;
                    if (mat == 0) {
                        __half* Qh = Qs + head*64*QP;
                        *reinterpret_cast<__half2*>(Qh + row*QP + d) =
                            __floats2half2_rn(c[mt][p][0] + b0, c[mt][p][1] + b1);
                        *reinterpret_cast<__half2*>(Qh + (row+8)*QP + d) =
                            __floats2half2_rn(c[mt][p][2] + b0, c[mt][p][3] + b1);
                    } else if (mat == 1) {
                        __half* Kh = Ks + head*64*QP;
                        *reinterpret_cast<__half2*>(Kh + row*QP + d) =
                            __floats2half2_rn(c[mt][p][0] + b0, c[mt][p][1] + b1);
                        *reinterpret_cast<__half2*>(Kh + (row+8)*QP + d) =
                            __floats2half2_rn(c[mt][p][2] + b0, c[mt][p][3] + b1);
                    } else {
                        __half* Vh = Vt + head*32*VP;
                        Vh[d*VP + row]         = __float2half_rn(c[mt][p][0] + b0);
                        Vh[(d+1)*VP + row]     = __float2half_rn(c[mt][p][1] + b1);
                        Vh[d*VP + row + 8]     = __float2half_rn(c[mt][p][2] + b0);
                        Vh[(d+1)*VP + row + 8] = __float2half_rn(c[mt][p][3] + b1);
                    }
                }
            }
        }
        __syncthreads();

        // ---- attention: warp = (head, 32-row half); softmax in registers ----
        {
            const int h = wid >> 1, r0 = (wid & 1) * 32;
            const __half* Qh = Qs + h*64*QP;
            const __half* Kh = Ks + h*64*QP;
            const __half* Vh = Vt + h*32*VP;

            float s[2][8][4];
            #pragma unroll
            for (int mt = 0; mt < 2; ++mt)
                #pragma unroll
                for (int nt = 0; nt < 8; ++nt)
                    s[mt][nt][0] = s[mt][nt][1] = s[mt][nt][2] = s[mt][nt][3] = 0.f;

            #pragma unroll
            for (int kt = 0; kt < 2; ++kt) {
                int k0 = kt * 16;
                unsigned a[2][4];
                #pragma unroll
                for (int mt = 0; mt < 2; ++mt) {
                    const __half* Ab = Qh + (r0 + mt*16 + g)*QP + 2*tg + k0;
                    a[mt][0] = ld_h2(Ab);
                    a[mt][1] = ld_h2(Ab + 8*QP);
                    a[mt][2] = ld_h2(Ab + 8);
                    a[mt][3] = ld_h2(Ab + 8*QP + 8);
                }
                #pragma unroll
                for (int nt = 0; nt < 8; ++nt) {
                    const __half* Bb = Kh + (nt*8 + g)*QP + 2*tg + k0;
                    unsigned b0 = ld_h2(Bb), b1 = ld_h2(Bb + 8);
                    #pragma unroll
                    for (int mt = 0; mt < 2; ++mt)
                        mma_f16(s[mt][nt][0], s[mt][nt][1], s[mt][nt][2], s[mt][nt][3],
                                a[mt][0], a[mt][1], a[mt][2], a[mt][3], b0, b1);
                }
            }

            // scale + bias + rowwise softmax (4 lanes per row via shfl)
            #pragma unroll
            for (int mt = 0; mt < 2; ++mt) {
                #pragma unroll
                for (int rr = 0; rr < 2; ++rr) {
                    int row = r0 + mt*16 + g + rr*8;
                    float m = -1e30f;
                    #pragma unroll
                    for (int nt = 0; nt < 8; ++nt) {
                        #pragma unroll
                        for (int q = 0; q < 2; ++q) {
                            int col = nt*8 + 2*tg + q;
                            float v = s[mt][nt][rr*2+q] * scale + bias_at(Bs, h, row, col);
                            s[mt][nt][rr*2+q] = v;
                            m = fmaxf(m, v);
                        }
                    }
                    m = fmaxf(m, __shfl_xor_sync(0xffffffffu, m, 1));
                    m = fmaxf(m, __shfl_xor_sync(0xffffffffu, m, 2));
                    float sum = 0.f;
                    #pragma unroll
                    for (int nt = 0; nt < 8; ++nt) {
                        #pragma unroll
                        for (int q = 0; q < 2; ++q) {
                            float e = __expf(s[mt][nt][rr*2+q] - m);
                            s[mt][nt][rr*2+q] = e;
                            sum += e;
                        }
                    }
                    sum += __shfl_xor_sync(0xffffffffu, sum, 1);
                    sum += __shfl_xor_sync(0xffffffffu, sum, 2);
                    float inv = 1.0f / sum;
                    #pragma unroll
                    for (int nt = 0; nt < 8; ++nt) {
                        s[mt][nt][rr*2+0] *= inv;
                        s[mt][nt][rr*2+1] *= inv;
                    }
                }
            }

            // repack probs (c-frag) as A-frags for PV
            unsigned af[2][4][4];
            #pragma unroll
            for (int mt = 0; mt < 2; ++mt)
                #pragma unroll
                for (int kt = 0; kt < 4; ++kt) {
                    __half2 h0 = __floats2half2_rn(s[mt][2*kt][0],   s[mt][2*kt][1]);
                    __half2 h1 = __floats2half2_rn(s[mt][2*kt][2],   s[mt][2*kt][3]);
                    __half2 h2 = __floats2half2_rn(s[mt][2*kt+1][0], s[mt][2*kt+1][1]);
                    __half2 h3 = __floats2half2_rn(s[mt][2*kt+1][2], s[mt][2*kt+1][3]);
                    af[mt][kt][0] = *reinterpret_cast<unsigned*>(&h0);
                    af[mt][kt][1] = *reinterpret_cast<unsigned*>(&h1);
                    af[mt][kt][2] = *reinterpret_cast<unsigned*>(&h2);
                    af[mt][kt][3] = *reinterpret_cast<unsigned*>(&h3);
                }

            // O = P @ V  (B-frags from Vt)
            float o[2][4][4];
            #pragma unroll
            for (int mt = 0; mt < 2; ++mt)
                #pragma unroll
                for (int nt = 0; nt < 4; ++nt)
                    o[mt][nt][0] = o[mt][nt][1] = o[mt][nt][2] = o[mt][nt][3] = 0.f;

            #pragma unroll
            for (int kt = 0; kt < 4; ++kt) {
                #pragma unroll
                for (int nt = 0; nt < 4; ++nt) {
                    const __half* Bb = Vh + (nt*8 + g)*VP + 2*tg + kt*16;
                    unsigned b0 = ld_h2(Bb), b1 = ld_h2(Bb + 8);
                    #pragma unroll
                    for (int mt = 0; mt < 2; ++mt)
                        mma_f16(o[mt][nt][0], o[mt][nt][1], o[mt][nt][2], o[mt][nt][3],
                                af[mt][kt][0], af[mt][kt][1], af[mt][kt][2], af[mt][kt][3],
                                b0, b1);
                }
            }
            // write O into Xs (input dead now)
            #pragma unroll
            for (int mt = 0; mt < 2; ++mt)
                #pragma unroll
                for (int nt = 0; nt < 4; ++nt) {
                    int col = h*32 + nt*8 + 2*tg;
                    int row = r0 + mt*16 + g;
                    *reinterpret_cast<__half2*>(Xs + row*XP + col) =
                        __floats2half2_rn(o[mt][nt][0], o[mt][nt][1]);
                    *reinterpret_cast<__half2*>(Xs + (row+8)*XP + col) =
                        __floats2half2_rn(o[mt][nt][2], o[mt][nt][3]);
                }
        }
        __syncthreads();

        // ---- proj: [64x128]@[128x128]; warp = 32 rows x 32 cols; scatter store ----
        {
            const int mh = wid >> 2, nq = wid & 3;
            float c[2][4][4];
            #pragma unroll
            for (int mt = 0; mt < 2; ++mt)
                #pragma unroll
                for (int nt = 0; nt < 4; ++nt)
                    c[mt][nt][0] = c[mt][nt][1] = c[mt][nt][2] = c[mt][nt][3] = 0.f;

            #pragma unroll
            for (int ks = 0; ks < 8; ++ks) {
                int k0 = ks * 16;
                unsigned a[2][4];
                #pragma unroll
                for (int mt = 0; mt < 2; ++mt) {
                    const __half* Ab = Xs + (mh*32 + mt*16 + g)*XP + 2*tg + k0;
                    a[mt][0] = ld_h2(Ab);
                    a[mt][1] = ld_h2(Ab + 8*XP);
                    a[mt][2] = ld_h2(Ab + 8);
                    a[mt][3] = ld_h2(Ab + 8*XP + 8);
                }
                #pragma unroll
                for (int nt = 0; nt < 4; ++nt) {
                    const __half* Bb = Wp + (nq*32 + nt*8 + g)*WPP + 2*tg + k0;
                    unsigned b0 = ld_h2(Bb), b1 = ld_h2(Bb + 8);
                    #pragma unroll
                    for (int mt = 0; mt < 2; ++mt)
                        mma_f16(c[mt][nt][0], c[mt][nt][1], c[mt][nt][2], c[mt][nt][3],
                                a[mt][0], a[mt][1], a[mt][2], a[mt][3], b0, b1);
                }
            }
            #pragma unroll
            for (int mt = 0; mt < 2; ++mt)
                #pragma unroll
                for (int nt = 0; nt < 4; ++nt) {
                    int col = nq*32 + nt*8 + 2*tg;
                    float b0 = pb[col], b1 = pb[col + 1];
                    #pragma unroll
                    for (int rr = 0; rr < 2; ++rr) {
                        int t = mh*32 + mt*16 + g + rr*8;
                        int i = t >> 3, j = t & 7;
                        int gr = (wh*8 + i + SHIFTV) & 511;
                        int gc = (ww*8 + j + SHIFTV) & 511;
                        float2 st;
                        st.x = c[mt][nt][rr*2+0] + b0;
                        st.y = c[mt][nt][rr*2+1] + b1;
                        *reinterpret_cast<float2*>(
                            out + (((size_t)b*512 + gr)*512 + gc)*128 + col) = st;
                    }
                }
        }
    }
}

extern "C" void kernel_launch(void* const* d_in, const int* in_sizes, int n_in,
                              void* d_out, int out_size)
{
    const float* x          = (const float*)d_in[0];
    const float* qkv_w      = (const float*)d_in[1];
    const float* qkv_b      = (const float*)d_in[2];
    const float* proj_w     = (const float*)d_in[3];
    const float* proj_b     = (const float*)d_in[4];
    const float* bias_table = (const float*)d_in[5];
    float* out = (float*)d_out;

    prep_qkv<<<(384*128 + 255)/256, 256>>>(qkv_w);
    prep_proj<<<(128*128 + 255)/256, 256>>>(proj_w);

    cudaFuncSetAttribute(swin_win_attn_kernel,
                         cudaFuncAttributeMaxDynamicSharedMemorySize, SMEM_BYTES);
    swin_win_attn_kernel<<<16384/NW, 256, SMEM_BYTES>>>(
        x, qkv_b, proj_b, bias_table, out);
}

// round 4
// speedup vs baseline: 2.3046x; 1.6000x over previous
#include <cuda_runtime.h>
#include <cuda_fp16.h>

#define SHIFTV 4
#define HEADS 4
#define NW 8          // windows per CTA
#define NTHREADS 512

// pitches in __half units; word-pitch % 8 == 4 -> conflict-free frag access
#define XP 136   // Xs (input / attention-output overlay) [64][128]
#define WQP 136  // WqkvT [384][128]
#define WPP 136  // WprojT [128][128]
#define QP 40    // Qs/Ks per head [64][32]
#define VP 72    // Vt per head [32 d-rows][64 tokens] (+pad)

#define H_WQ   (384*WQP)
#define H_WP   (128*WPP)
#define H_X    (64*XP)
#define H_Q    (HEADS*64*QP)
#define H_K    (HEADS*64*QP)
#define H_V    (HEADS*32*VP)
#define SMEM_HALVES (H_WQ + H_WP + H_X + H_Q + H_K + H_V)
#define SMEM_FLOATS (225*HEADS + 384 + 128)
#define SMEM_BYTES  (SMEM_HALVES*2 + SMEM_FLOATS*4)

__device__ __align__(16) __half g_qkvT[384*128];
__device__ __align__(16) __half g_projT[128*128];

__global__ void prep_qkv(const float* __restrict__ w) {
    int i = blockIdx.x * 256 + threadIdx.x;
    if (i < 384*128) {
        int n = i >> 7, k = i & 127;
        g_qkvT[i] = __float2half_rn(w[k*384 + n]);
    }
}
__global__ void prep_proj(const float* __restrict__ w) {
    int i = blockIdx.x * 256 + threadIdx.x;
    if (i < 128*128) {
        int n = i >> 7, k = i & 127;
        g_projT[i] = __float2half_rn(w[k*128 + n]);
    }
}

__device__ __forceinline__ void mma_f16(float& c0, float& c1, float& c2, float& c3,
                                        unsigned a0, unsigned a1, unsigned a2, unsigned a3,
                                        unsigned b0, unsigned b1) {
    asm volatile(
        "mma.sync.aligned.m16n8k16.row.col.f32.f16.f16.f32 "
        "{%0,%1,%2,%3},{%4,%5,%6,%7},{%8,%9},{%0,%1,%2,%3};\n"
        : "+f"(c0), "+f"(c1), "+f"(c2), "+f"(c3)
        : "r"(a0), "r"(a1), "r"(a2), "r"(a3), "r"(b0), "r"(b1));
}

__device__ __forceinline__ unsigned ld_h2(const __half* p) {
    return *reinterpret_cast<const unsigned*>(p);
}

__device__ __forceinline__ float bias_at(const float* Bs, int h, int i, int j) {
    int idx = ((i >> 3) - (j >> 3) + 7) * 15 + ((i & 7) - (j & 7) + 7);
    return Bs[idx * HEADS + h];
}

__global__ __launch_bounds__(NTHREADS, 1) void swin_win_attn_kernel(
    const float* __restrict__ x, const float* __restrict__ qkv_b,
    const float* __restrict__ proj_b, const float* __restrict__ bias_table,
    float* __restrict__ out)
{
    extern __shared__ char smem_raw[];
    __half* Wq = reinterpret_cast<__half*>(smem_raw);
    __half* Wp = Wq + H_WQ;
    __half* Xs = Wp + H_WP;      // input window; later attention output O
    __half* Qs = Xs + H_X;
    __half* Ks = Qs + H_Q;
    __half* Vt = Ks + H_K;
    float*  Bs = reinterpret_cast<float*>(Vt + H_V);
    float*  qb = Bs + 225*HEADS;
    float*  pb = qb + 384;

    const int tid = threadIdx.x, lane = tid & 31, wid = tid >> 5;
    const int g = lane >> 2, tg = lane & 3;

    // ---- one-time per CTA: resident weights (vectorized) + biases ----
    {
        const uint4* src = reinterpret_cast<const uint4*>(g_qkvT);
        for (int i = tid; i < 384*16; i += NTHREADS) {
            int r = i >> 4, c = i & 15;
            *reinterpret_cast<uint4*>(Wq + r*WQP + c*8) = src[i];
        }
        const uint4* src2 = reinterpret_cast<const uint4*>(g_projT);
        for (int i = tid; i < 128*16; i += NTHREADS) {
            int r = i >> 4, c = i & 15;
            *reinterpret_cast<uint4*>(Wp + r*WPP + c*8) = src2[i];
        }
        for (int i = tid; i < 225*HEADS; i += NTHREADS) Bs[i] = bias_table[i];
        if (tid < 384) qb[tid] = qkv_b[tid];
        if (tid < 128) pb[tid] = proj_b[tid];
    }

    const float scale = 0.17677669529663687f;  // 32^-0.5

    // register-pipelined gather: this thread's 4 tokens x 8 halves
    unsigned hreg[8];
    const int c4 = (lane) * 4;          // column base (x4 floats)
    auto gather_regs = [&](int widx) {
        int bb = widx >> 12, wh = (widx >> 6) & 63, ww = widx & 63;
        #pragma unroll
        for (int k = 0; k < 4; ++k) {
            int t = wid + k * 16;       // token 0..63
            int i = t >> 3, j = t & 7;
            int gr = (wh*8 + i + SHIFTV) & 511;
            int gc = (ww*8 + j + SHIFTV) & 511;
            float4 v = *reinterpret_cast<const float4*>(
                x + (((size_t)bb*512 + gr)*512 + gc)*128 + c4);
            __half2 h0 = __floats2half2_rn(v.x, v.y);
            __half2 h1 = __floats2half2_rn(v.z, v.w);
            hreg[k*2]   = *reinterpret_cast<unsigned*>(&h0);
            hreg[k*2+1] = *reinterpret_cast<unsigned*>(&h1);
        }
    };
    auto store_regs = [&]() {
        #pragma unroll
        for (int k = 0; k < 4; ++k) {
            int t = wid + k * 16;
            *reinterpret_cast<unsigned*>(Xs + t*XP + c4)     = hreg[k*2];
            *reinterpret_cast<unsigned*>(Xs + t*XP + c4 + 2) = hreg[k*2+1];
        }
    };

    gather_regs(blockIdx.x * NW);

    for (int wi = 0; wi < NW; ++wi) {
        const int widx = blockIdx.x * NW + wi;
        const int b = widx >> 12, wh = (widx >> 6) & 63, ww = widx & 63;

        __syncthreads();   // Xs free (prev proj done); first iter: weights loaded
        store_regs();
        __syncthreads();

        // ---- QKV: [64x128]@[128x384]; warp = 32 rows x 48 cols ----
        {
            const int rh = wid & 1, cb = (wid >> 1) * 48;
            float c[2][6][4];
            #pragma unroll
            for (int mt = 0; mt < 2; ++mt)
                #pragma unroll
                for (int p = 0; p < 6; ++p)
                    c[mt][p][0] = c[mt][p][1] = c[mt][p][2] = c[mt][p][3] = 0.f;

            #pragma unroll
            for (int ks = 0; ks < 8; ++ks) {
                int k0 = ks * 16;
                unsigned a[2][4];
                #pragma unroll
                for (int mt = 0; mt < 2; ++mt) {
                    const __half* Ab = Xs + (rh*32 + mt*16 + g)*XP + 2*tg + k0;
                    a[mt][0] = ld_h2(Ab);
                    a[mt][1] = ld_h2(Ab + 8*XP);
                    a[mt][2] = ld_h2(Ab + 8);
                    a[mt][3] = ld_h2(Ab + 8*XP + 8);
                }
                #pragma unroll
                for (int p = 0; p < 6; ++p) {
                    const __half* Bb = Wq + (cb + p*8 + g)*WQP + 2*tg + k0;
                    unsigned b0 = ld_h2(Bb), b1 = ld_h2(Bb + 8);
                    #pragma unroll
                    for (int mt = 0; mt < 2; ++mt)
                        mma_f16(c[mt][p][0], c[mt][p][1], c[mt][p][2], c[mt][p][3],
                                a[mt][0], a[mt][1], a[mt][2], a[mt][3], b0, b1);
                }
            }
            // epilogue: route to Q / K / V(T) with bias
            #pragma unroll
            for (int p = 0; p < 6; ++p) {
                int col = cb + p*8 + 2*tg;
                int mat = col >> 7, head = (col >> 5) & 3, d = col & 31;
                float b0 = qb[col], b1 = qb[col + 1];
                #pragma unroll
                for (int mt = 0; mt < 2; ++mt) {
                    int row = rh*32 + mt*16 + g;
                    if (mat == 0) {
                        __half* Qh = Qs + head*64*QP;
                        *reinterpret_cast<__half2*>(Qh + row*QP + d) =
                            __floats2half2_rn(c[mt][p][0] + b0, c[mt][p][1] + b1);
                        *reinterpret_cast<__half2*>(Qh + (row+8)*QP + d) =
                            __floats2half2_rn(c[mt][p][2] + b0, c[mt][p][3] + b1);
                    } else if (mat == 1) {
                        __half* Kh = Ks + head*64*QP;
                        *reinterpret_cast<__half2*>(Kh + row*QP + d) =
                            __floats2half2_rn(c[mt][p][0] + b0, c[mt][p][1] + b1);
                        *reinterpret_cast<__half2*>(Kh + (row+8)*QP + d) =
                            __floats2half2_rn(c[mt][p][2] + b0, c[mt][p][3] + b1);
                    } else {
                        __half* Vh = Vt + head*32*VP;
                        Vh[d*VP + row]         = __float2half_rn(c[mt][p][0] + b0);
                        Vh[(d+1)*VP + row]     = __float2half_rn(c[mt][p][1] + b1);
                        Vh[d*VP + row + 8]     = __float2half_rn(c[mt][p][2] + b0);
                        Vh[(d+1)*VP + row + 8] = __float2half_rn(c[mt][p][3] + b1);
                    }
                }
            }
        }
        __syncthreads();

        // prefetch next window's input into registers (hidden behind attn+proj)
        if (wi + 1 < NW) gather_regs(widx + 1);

        // ---- attention: warp = (head, 16-row quarter); softmax in registers ----
        {
            const int h = wid >> 2, r0 = (wid & 3) * 16;
            const __half* Qh = Qs + h*64*QP;
            const __half* Kh = Ks + h*64*QP;
            const __half* Vh = Vt + h*32*VP;

            float s[8][4];
            #pragma unroll
            for (int nt = 0; nt < 8; ++nt)
                s[nt][0] = s[nt][1] = s[nt][2] = s[nt][3] = 0.f;

            #pragma unroll
            for (int kt = 0; kt < 2; ++kt) {
                int k0 = kt * 16;
                unsigned a[4];
                const __half* Ab = Qh + (r0 + g)*QP + 2*tg + k0;
                a[0] = ld_h2(Ab);
                a[1] = ld_h2(Ab + 8*QP);
                a[2] = ld_h2(Ab + 8);
                a[3] = ld_h2(Ab + 8*QP + 8);
                #pragma unroll
                for (int nt = 0; nt < 8; ++nt) {
                    const __half* Bb = Kh + (nt*8 + g)*QP + 2*tg + k0;
                    mma_f16(s[nt][0], s[nt][1], s[nt][2], s[nt][3],
                            a[0], a[1], a[2], a[3], ld_h2(Bb), ld_h2(Bb + 8));
                }
            }

            // scale + bias + rowwise softmax (4 lanes per row via shfl)
            #pragma unroll
            for (int rr = 0; rr < 2; ++rr) {
                int row = r0 + g + rr*8;
                float m = -1e30f;
                #pragma unroll
                for (int nt = 0; nt < 8; ++nt) {
                    #pragma unroll
                    for (int q = 0; q < 2; ++q) {
                        int col = nt*8 + 2*tg + q;
                        float v = s[nt][rr*2+q] * scale + bias_at(Bs, h, row, col);
                        s[nt][rr*2+q] = v;
                        m = fmaxf(m, v);
                    }
                }
                m = fmaxf(m, __shfl_xor_sync(0xffffffffu, m, 1));
                m = fmaxf(m, __shfl_xor_sync(0xffffffffu, m, 2));
                float sum = 0.f;
                #pragma unroll
                for (int nt = 0; nt < 8; ++nt) {
                    #pragma unroll
                    for (int q = 0; q < 2; ++q) {
                        float e = __expf(s[nt][rr*2+q] - m);
                        s[nt][rr*2+q] = e;
                        sum += e;
                    }
                }
                sum += __shfl_xor_sync(0xffffffffu, sum, 1);
                sum += __shfl_xor_sync(0xffffffffu, sum, 2);
                float inv = 1.0f / sum;
                #pragma unroll
                for (int nt = 0; nt < 8; ++nt) {
                    s[nt][rr*2+0] *= inv;
                    s[nt][rr*2+1] *= inv;
                }
            }

            // repack probs (c-frag) as A-frags for PV
            unsigned af[4][4];
            #pragma unroll
            for (int kt = 0; kt < 4; ++kt) {
                __half2 h0 = __floats2half2_rn(s[2*kt][0],   s[2*kt][1]);
                __half2 h1 = __floats2half2_rn(s[2*kt][2],   s[2*kt][3]);
                __half2 h2 = __floats2half2_rn(s[2*kt+1][0], s[2*kt+1][1]);
                __half2 h3 = __floats2half2_rn(s[2*kt+1][2], s[2*kt+1][3]);
                af[kt][0] = *reinterpret_cast<unsigned*>(&h0);
                af[kt][1] = *reinterpret_cast<unsigned*>(&h1);
                af[kt][2] = *reinterpret_cast<unsigned*>(&h2);
                af[kt][3] = *reinterpret_cast<unsigned*>(&h3);
            }

            // O = P @ V  (B-frags from Vt)
            float o[4][4];
            #pragma unroll
            for (int nt = 0; nt < 4; ++nt)
                o[nt][0] = o[nt][1] = o[nt][2] = o[nt][3] = 0.f;

            #pragma unroll
            for (int kt = 0; kt < 4; ++kt) {
                #pragma unroll
                for (int nt = 0; nt < 4; ++nt) {
                    const __half* Bb = Vh + (nt*8 + g)*VP + 2*tg + kt*16;
                    mma_f16(o[nt][0], o[nt][1], o[nt][2], o[nt][3],
                            af[kt][0], af[kt][1], af[kt][2], af[kt][3],
                            ld_h2(Bb), ld_h2(Bb + 8));
                }
            }
            // write O into Xs (input dead now)
            #pragma unroll
            for (int nt = 0; nt < 4; ++nt) {
                int col = h*32 + nt*8 + 2*tg;
                int row = r0 + g;
                *reinterpret_cast<__half2*>(Xs + row*XP + col) =
                    __floats2half2_rn(o[nt][0], o[nt][1]);
                *reinterpret_cast<__half2*>(Xs + (row+8)*XP + col) =
                    __floats2half2_rn(o[nt][2], o[nt][3]);
            }
        }
        __syncthreads();

        // ---- proj: [64x128]@[128x128]; warp = 16 rows x 32 cols; scatter store ----
        {
            const int mh = wid >> 2, nq = wid & 3;
            float c[4][4];
            #pragma unroll
            for (int nt = 0; nt < 4; ++nt)
                c[nt][0] = c[nt][1] = c[nt][2] = c[nt][3] = 0.f;

            #pragma unroll
            for (int ks = 0; ks < 8; ++ks) {
                int k0 = ks * 16;
                unsigned a[4];
                const __half* Ab = Xs + (mh*16 + g)*XP + 2*tg + k0;
                a[0] = ld_h2(Ab);
                a[1] = ld_h2(Ab + 8*XP);
                a[2] = ld_h2(Ab + 8);
                a[3] = ld_h2(Ab + 8*XP + 8);
                #pragma unroll
                for (int nt = 0; nt < 4; ++nt) {
                    const __half* Bb = Wp + (nq*32 + nt*8 + g)*WPP + 2*tg + k0;
                    mma_f16(c[nt][0], c[nt][1], c[nt][2], c[nt][3],
                            a[0], a[1], a[2], a[3], ld_h2(Bb), ld_h2(Bb + 8));
                }
            }
            #pragma unroll
            for (int nt = 0; nt < 4; ++nt) {
                int col = nq*32 + nt*8 + 2*tg;
                float b0 = pb[col], b1 = pb[col + 1];
                #pragma unroll
                for (int rr = 0; rr < 2; ++rr) {
                    int t = mh*16 + g + rr*8;
                    int i = t >> 3, j = t & 7;
                    int gr = (wh*8 + i + SHIFTV) & 511;
                    int gc = (ww*8 + j + SHIFTV) & 511;
                    float2 st;
                    st.x = c[nt][rr*2+0] + b0;
                    st.y = c[nt][rr*2+1] + b1;
                    *reinterpret_cast<float2*>(
                        out + (((size_t)b*512 + gr)*512 + gc)*128 + col) = st;
                }
            }
        }
    }
}

extern "C" void kernel_launch(void* const* d_in, const int* in_sizes, int n_in,
                              void* d_out, int out_size)
{
    const float* x          = (const float*)d_in[0];
    const float* qkv_w      = (const float*)d_in[1];
    const float* qkv_b      = (const float*)d_in[2];
    const float* proj_w     = (const float*)d_in[3];
    const float* proj_b     = (const float*)d_in[4];
    const float* bias_table = (const float*)d_in[5];
    float* out = (float*)d_out;

    prep_qkv<<<(384*128 + 255)/256, 256>>>(qkv_w);
    prep_proj<<<(128*128 + 255)/256, 256>>>(proj_w);

    cudaFuncSetAttribute(swin_win_attn_kernel,
                         cudaFuncAttributeMaxDynamicSharedMemorySize, SMEM_BYTES);
    swin_win_attn_kernel<<<16384/NW, NTHREADS, SMEM_BYTES>>>(
        x, qkv_b, proj_b, bias_table, out);
}

// round 5
// speedup vs baseline: 2.3101x; 1.0024x over previous
#include <cuda_runtime.h>
#include <cuda_fp16.h>

#define SHIFTV 4
#define HEADS 4
#define NW 8          // windows per CTA
#define NTHREADS 512

// pitches in __half units; word-pitch % 8 == 4 -> conflict-free frag access
#define XP 136   // Xs (input / attention-output overlay) [64][128]
#define WQP 136  // WqkvT [384][128]
#define WPP 136  // WprojT [128][128]
#define QP 40    // Qs/Ks per head [64][32]
#define VP 72    // Vt per head [32 d-rows][64 tokens] (+pad)

#define H_WQ   (384*WQP)
#define H_WP   (128*WPP)
#define H_X    (64*XP)
#define H_Q    (HEADS*64*QP)
#define H_K    (HEADS*64*QP)
#define H_V    (HEADS*32*VP)
#define SMEM_HALVES (H_WQ + H_WP + H_X + H_Q + H_K + H_V)
#define SMEM_FLOATS (225*HEADS + 384 + 128)
#define SMEM_BYTES  (SMEM_HALVES*2 + SMEM_FLOATS*4)

__device__ __align__(16) __half g_qkvT[384*128];
__device__ __align__(16) __half g_projT[128*128];

__global__ void prep_qkv(const float* __restrict__ w) {
    int i = blockIdx.x * 256 + threadIdx.x;
    if (i < 384*128) {
        int n = i >> 7, k = i & 127;
        g_qkvT[i] = __float2half_rn(w[k*384 + n]);
    }
}
__global__ void prep_proj(const float* __restrict__ w) {
    int i = blockIdx.x * 256 + threadIdx.x;
    if (i < 128*128) {
        int n = i >> 7, k = i & 127;
        g_projT[i] = __float2half_rn(w[k*128 + n]);
    }
}

__device__ __forceinline__ void mma_f16(float& c0, float& c1, float& c2, float& c3,
                                        unsigned a0, unsigned a1, unsigned a2, unsigned a3,
                                        unsigned b0, unsigned b1) {
    asm volatile(
        "mma.sync.aligned.m16n8k16.row.col.f32.f16.f16.f32 "
        "{%0,%1,%2,%3},{%4,%5,%6,%7},{%8,%9},{%0,%1,%2,%3};\n"
        : "+f"(c0), "+f"(c1), "+f"(c2), "+f"(c3)
        : "r"(a0), "r"(a1), "r"(a2), "r"(a3), "r"(b0), "r"(b1));
}

__device__ __forceinline__ unsigned ld_h2(const __half* p) {
    return *reinterpret_cast<const unsigned*>(p);
}

__device__ __forceinline__ float bias_at(const float* Bs, int h, int i, int j) {
    int idx = ((i >> 3) - (j >> 3) + 7) * 15 + ((i & 7) - (j & 7) + 7);
    return Bs[idx * HEADS + h];
}

__global__ __launch_bounds__(NTHREADS, 1) void swin_win_attn_kernel(
    const float* __restrict__ x, const float* __restrict__ qkv_b,
    const float* __restrict__ proj_b, const float* __restrict__ bias_table,
    float* __restrict__ out)
{
    extern __shared__ char smem_raw[];
    __half* Wq = reinterpret_cast<__half*>(smem_raw);
    __half* Wp = Wq + H_WQ;
    __half* Xs = Wp + H_WP;      // input window; later attention output O
    __half* Qs = Xs + H_X;
    __half* Ks = Qs + H_Q;
    __half* Vt = Ks + H_K;
    float*  Bs = reinterpret_cast<float*>(Vt + H_V);
    float*  qb = Bs + 225*HEADS;
    float*  pb = qb + 384;

    const int tid = threadIdx.x, lane = tid & 31, wid = tid >> 5;
    const int g = lane >> 2, tg = lane & 3;

    // ---- one-time per CTA: resident weights (vectorized) + biases ----
    {
        const uint4* src = reinterpret_cast<const uint4*>(g_qkvT);
        for (int i = tid; i < 384*16; i += NTHREADS) {
            int r = i >> 4, c = i & 15;
            *reinterpret_cast<uint4*>(Wq + r*WQP + c*8) = src[i];
        }
        const uint4* src2 = reinterpret_cast<const uint4*>(g_projT);
        for (int i = tid; i < 128*16; i += NTHREADS) {
            int r = i >> 4, c = i & 15;
            *reinterpret_cast<uint4*>(Wp + r*WPP + c*8) = src2[i];
        }
        for (int i = tid; i < 225*HEADS; i += NTHREADS) Bs[i] = bias_table[i];
        if (tid < 384) qb[tid] = qkv_b[tid];
        if (tid < 128) pb[tid] = proj_b[tid];
    }

    const float scale = 0.17677669529663687f;  // 32^-0.5

    // register-pipelined gather: this thread's 4 tokens x 8 halves
    unsigned hreg[8];
    const int c4 = (lane) * 4;          // column base (x4 floats)
    auto gather_regs = [&](int widx) {
        int bb = widx >> 12, wh = (widx >> 6) & 63, ww = widx & 63;
        #pragma unroll
        for (int k = 0; k < 4; ++k) {
            int t = wid + k * 16;       // token 0..63
            int i = t >> 3, j = t & 7;
            int gr = (wh*8 + i + SHIFTV) & 511;
            int gc = (ww*8 + j + SHIFTV) & 511;
            float4 v = *reinterpret_cast<const float4*>(
                x + (((size_t)bb*512 + gr)*512 + gc)*128 + c4);
            __half2 h0 = __floats2half2_rn(v.x, v.y);
            __half2 h1 = __floats2half2_rn(v.z, v.w);
            hreg[k*2]   = *reinterpret_cast<unsigned*>(&h0);
            hreg[k*2+1] = *reinterpret_cast<unsigned*>(&h1);
        }
    };
    auto store_regs = [&]() {
        #pragma unroll
        for (int k = 0; k < 4; ++k) {
            int t = wid + k * 16;
            *reinterpret_cast<unsigned*>(Xs + t*XP + c4)     = hreg[k*2];
            *reinterpret_cast<unsigned*>(Xs + t*XP + c4 + 2) = hreg[k*2+1];
        }
    };

    gather_regs(blockIdx.x * NW);

    for (int wi = 0; wi < NW; ++wi) {
        const int widx = blockIdx.x * NW + wi;
        const int b = widx >> 12, wh = (widx >> 6) & 63, ww = widx & 63;

        __syncthreads();   // Xs free (prev proj done); first iter: weights loaded
        store_regs();
        __syncthreads();

        // ---- QKV: [64x128]@[128x384]; warp = 32 rows x 48 cols ----
        {
            const int rh = wid & 1, cb = (wid >> 1) * 48;
            float c[2][6][4];
            #pragma unroll
            for (int mt = 0; mt < 2; ++mt)
                #pragma unroll
                for (int p = 0; p < 6; ++p)
                    c[mt][p][0] = c[mt][p][1] = c[mt][p][2] = c[mt][p][3] = 0.f;

            #pragma unroll
            for (int ks = 0; ks < 8; ++ks) {
                int k0 = ks * 16;
                unsigned a[2][4];
                #pragma unroll
                for (int mt = 0; mt < 2; ++mt) {
                    const __half* Ab = Xs + (rh*32 + mt*16 + g)*XP + 2*tg + k0;
                    a[mt][0] = ld_h2(Ab);
                    a[mt][1] = ld_h2(Ab + 8*XP);
                    a[mt][2] = ld_h2(Ab + 8);
                    a[mt][3] = ld_h2(Ab + 8*XP + 8);
                }
                #pragma unroll
                for (int p = 0; p < 6; ++p) {
                    const __half* Bb = Wq + (cb + p*8 + g)*WQP + 2*tg + k0;
                    unsigned b0 = ld_h2(Bb), b1 = ld_h2(Bb + 8);
                    #pragma unroll
                    for (int mt = 0; mt < 2; ++mt)
                        mma_f16(c[mt][p][0], c[mt][p][1], c[mt][p][2], c[mt][p][3],
                                a[mt][0], a[mt][1], a[mt][2], a[mt][3], b0, b1);
                }
            }
            // epilogue: route to Q / K / V(T) with bias
            #pragma unroll
            for (int p = 0; p < 6; ++p) {
                int col = cb + p*8 + 2*tg;
                int mat = col >> 7, head = (col >> 5) & 3, d = col & 31;
                float b0 = qb[col], b1 = qb[col + 1];
                #pragma unroll
                for (int mt = 0; mt < 2; ++mt) {
                    int row = rh*32 + mt*16 + g;
                    if (mat == 0) {
                        __half* Qh = Qs + head*64*QP;
                        *reinterpret_cast<__half2*>(Qh + row*QP + d) =
                            __floats2half2_rn(c[mt][p][0] + b0, c[mt][p][1] + b1);
                        *reinterpret_cast<__half2*>(Qh + (row+8)*QP + d) =
                            __floats2half2_rn(c[mt][p][2] + b0, c[mt][p][3] + b1);
                    } else if (mat == 1) {
                        __half* Kh = Ks + head*64*QP;
                        *reinterpret_cast<__half2*>(Kh + row*QP + d) =
                            __floats2half2_rn(c[mt][p][0] + b0, c[mt][p][1] + b1);
                        *reinterpret_cast<__half2*>(Kh + (row+8)*QP + d) =
                            __floats2half2_rn(c[mt][p][2] + b0, c[mt][p][3] + b1);
                    } else {
                        __half* Vh = Vt + head*32*VP;
                        Vh[d*VP + row]         = __float2half_rn(c[mt][p][0] + b0);
                        Vh[(d+1)*VP + row]     = __float2half_rn(c[mt][p][1] + b1);
                        Vh[d*VP + row + 8]     = __float2half_rn(c[mt][p][2] + b0);
                        Vh[(d+1)*VP + row + 8] = __float2half_rn(c[mt][p][3] + b1);
                    }
                }
            }
        }
        __syncthreads();

        // prefetch next window's input into registers (hidden behind attn+proj)
        if (wi + 1 < NW) gather_regs(widx + 1);

        // ---- attention: warp = (head, 16-row quarter); softmax in registers ----
        {
            const int h = wid >> 2, r0 = (wid & 3) * 16;
            const __half* Qh = Qs + h*64*QP;
            const __half* Kh = Ks + h*64*QP;
            const __half* Vh = Vt + h*32*VP;

            float s[8][4];
            #pragma unroll
            for (int nt = 0; nt < 8; ++nt)
                s[nt][0] = s[nt][1] = s[nt][2] = s[nt][3] = 0.f;

            #pragma unroll
            for (int kt = 0; kt < 2; ++kt) {
                int k0 = kt * 16;
                unsigned a[4];
                const __half* Ab = Qh + (r0 + g)*QP + 2*tg + k0;
                a[0] = ld_h2(Ab);
                a[1] = ld_h2(Ab + 8*QP);
                a[2] = ld_h2(Ab + 8);
                a[3] = ld_h2(Ab + 8*QP + 8);
                #pragma unroll
                for (int nt = 0; nt < 8; ++nt) {
                    const __half* Bb = Kh + (nt*8 + g)*QP + 2*tg + k0;
                    mma_f16(s[nt][0], s[nt][1], s[nt][2], s[nt][3],
                            a[0], a[1], a[2], a[3], ld_h2(Bb), ld_h2(Bb + 8));
                }
            }

            // scale + bias + rowwise softmax (4 lanes per row via shfl)
            #pragma unroll
            for (int rr = 0; rr < 2; ++rr) {
                int row = r0 + g + rr*8;
                float m = -1e30f;
                #pragma unroll
                for (int nt = 0; nt < 8; ++nt) {
                    #pragma unroll
                    for (int q = 0; q < 2; ++q) {
                        int col = nt*8 + 2*tg + q;
                        float v = s[nt][rr*2+q] * scale + bias_at(Bs, h, row, col);
                        s[nt][rr*2+q] = v;
                        m = fmaxf(m, v);
                    }
                }
                m = fmaxf(m, __shfl_xor_sync(0xffffffffu, m, 1));
                m = fmaxf(m, __shfl_xor_sync(0xffffffffu, m, 2));
                float sum = 0.f;
                #pragma unroll
                for (int nt = 0; nt < 8; ++nt) {
                    #pragma unroll
                    for (int q = 0; q < 2; ++q) {
                        float e = __expf(s[nt][rr*2+q] - m);
                        s[nt][rr*2+q] = e;
                        sum += e;
                    }
                }
                sum += __shfl_xor_sync(0xffffffffu, sum, 1);
                sum += __shfl_xor_sync(0xffffffffu, sum, 2);
                float inv = 1.0f / sum;
                #pragma unroll
                for (int nt = 0; nt < 8; ++nt) {
                    s[nt][rr*2+0] *= inv;
                    s[nt][rr*2+1] *= inv;
                }
            }

            // repack probs (c-frag) as A-frags for PV
            unsigned af[4][4];
            #pragma unroll
            for (int kt = 0; kt < 4; ++kt) {
                __half2 h0 = __floats2half2_rn(s[2*kt][0],   s[2*kt][1]);
                __half2 h1 = __floats2half2_rn(s[2*kt][2],   s[2*kt][3]);
                __half2 h2 = __floats2half2_rn(s[2*kt+1][0], s[2*kt+1][1]);
                __half2 h3 = __floats2half2_rn(s[2*kt+1][2], s[2*kt+1][3]);
                af[kt][0] = *reinterpret_cast<unsigned*>(&h0);
                af[kt][1] = *reinterpret_cast<unsigned*>(&h1);
                af[kt][2] = *reinterpret_cast<unsigned*>(&h2);
                af[kt][3] = *reinterpret_cast<unsigned*>(&h3);
            }

            // O = P @ V  (B-frags from Vt)
            float o[4][4];
            #pragma unroll
            for (int nt = 0; nt < 4; ++nt)
                o[nt][0] = o[nt][1] = o[nt][2] = o[nt][3] = 0.f;

            #pragma unroll
            for (int kt = 0; kt < 4; ++kt) {
                #pragma unroll
                for (int nt = 0; nt < 4; ++nt) {
                    const __half* Bb = Vh + (nt*8 + g)*VP + 2*tg + kt*16;
                    mma_f16(o[nt][0], o[nt][1], o[nt][2], o[nt][3],
                            af[kt][0], af[kt][1], af[kt][2], af[kt][3],
                            ld_h2(Bb), ld_h2(Bb + 8));
                }
            }
            // write O into Xs (input dead now)
            #pragma unroll
            for (int nt = 0; nt < 4; ++nt) {
                int col = h*32 + nt*8 + 2*tg;
                int row = r0 + g;
                *reinterpret_cast<__half2*>(Xs + row*XP + col) =
                    __floats2half2_rn(o[nt][0], o[nt][1]);
                *reinterpret_cast<__half2*>(Xs + (row+8)*XP + col) =
                    __floats2half2_rn(o[nt][2], o[nt][3]);
            }
        }
        __syncthreads();

        // ---- proj: [64x128]@[128x128]; warp = 16 rows x 32 cols; scatter store ----
        {
            const int mh = wid >> 2, nq = wid & 3;
            float c[4][4];
            #pragma unroll
            for (int nt = 0; nt < 4; ++nt)
                c[nt][0] = c[nt][1] = c[nt][2] = c[nt][3] = 0.f;

            #pragma unroll
            for (int ks = 0; ks < 8; ++ks) {
                int k0 = ks * 16;
                unsigned a[4];
                const __half* Ab = Xs + (mh*16 + g)*XP + 2*tg + k0;
                a[0] = ld_h2(Ab);
                a[1] = ld_h2(Ab + 8*XP);
                a[2] = ld_h2(Ab + 8);
                a[3] = ld_h2(Ab + 8*XP + 8);
                #pragma unroll
                for (int nt = 0; nt < 4; ++nt) {
                    const __half* Bb = Wp + (nq*32 + nt*8 + g)*WPP + 2*tg + k0;
                    mma_f16(c[nt][0], c[nt][1], c[nt][2], c[nt][3],
                            a[0], a[1], a[2], a[3], ld_h2(Bb), ld_h2(Bb + 8));
                }
            }
            #pragma unroll
            for (int nt = 0; nt < 4; ++nt) {
                int col = nq*32 + nt*8 + 2*tg;
                float b0 = pb[col], b1 = pb[col + 1];
                #pragma unroll
                for (int rr = 0; rr < 2; ++rr) {
                    int t = mh*16 + g + rr*8;
                    int i = t >> 3, j = t & 7;
                    int gr = (wh*8 + i + SHIFTV) & 511;
                    int gc = (ww*8 + j + SHIFTV) & 511;
                    float2 st;
                    st.x = c[nt][rr*2+0] + b0;
                    st.y = c[nt][rr*2+1] + b1;
                    *reinterpret_cast<float2*>(
                        out + (((size_t)b*512 + gr)*512 + gc)*128 + col) = st;
                }
            }
        }
    }
}

extern "C" void kernel_launch(void* const* d_in, const int* in_sizes, int n_in,
                              void* d_out, int out_size)
{
    const float* x          = (const float*)d_in[0];
    const float* qkv_w      = (const float*)d_in[1];
    const float* qkv_b      = (const float*)d_in[2];
    const float* proj_w     = (const float*)d_in[3];
    const float* proj_b     = (const float*)d_in[4];
    const float* bias_table = (const float*)d_in[5];
    float* out = (float*)d_out;

    prep_qkv<<<(384*128 + 255)/256, 256>>>(qkv_w);
    prep_proj<<<(128*128 + 255)/256, 256>>>(proj_w);

    cudaFuncSetAttribute(swin_win_attn_kernel,
                         cudaFuncAttributeMaxDynamicSharedMemorySize, SMEM_BYTES);
    swin_win_attn_kernel<<<16384/NW, NTHREADS, SMEM_BYTES>>>(
        x, qkv_b, proj_b, bias_table, out);
}

// round 6
// speedup vs baseline: 2.3681x; 1.0251x over previous
#include <cuda_runtime.h>
#include <cuda_fp16.h>

#define SHIFTV 4
#define HEADS 4
#define NW 8          // windows per CTA
#define NTHREADS 512

// pitches in __half units; all row strides 16B-aligned & ldmatrix-conflict-free
#define XP 136   // Xs (input / attention-output overlay) [64][128]
#define WQP 136  // WqkvT [384][128]
#define WPP 136  // WprojT [128][128]
#define QP 40    // Qs/Ks per head [64][32]
#define VP 72    // Vt per head [32 d-rows][64 tokens] (+pad)

#define H_WQ   (384*WQP)
#define H_WP   (128*WPP)
#define H_X    (64*XP)
#define H_Q    (HEADS*64*QP)
#define H_K    (HEADS*64*QP)
#define H_V    (HEADS*32*VP)
#define SMEM_HALVES (H_WQ + H_WP + H_X + H_Q + H_K + H_V)
#define SMEM_FLOATS (225*HEADS + 384 + 128)
#define SMEM_BYTES  (SMEM_HALVES*2 + SMEM_FLOATS*4)

__device__ __align__(16) __half g_qkvT[384*128];
__device__ __align__(16) __half g_projT[128*128];

__global__ void prep_qkv(const float* __restrict__ w) {
    int i = blockIdx.x * 256 + threadIdx.x;
    if (i < 384*128) {
        int n = i >> 7, k = i & 127;
        g_qkvT[i] = __float2half_rn(w[k*384 + n]);
    }
}
__global__ void prep_proj(const float* __restrict__ w) {
    int i = blockIdx.x * 256 + threadIdx.x;
    if (i < 128*128) {
        int n = i >> 7, k = i & 127;
        g_projT[i] = __float2half_rn(w[k*128 + n]);
    }
}

__device__ __forceinline__ void mma_f16(float& c0, float& c1, float& c2, float& c3,
                                        unsigned a0, unsigned a1, unsigned a2, unsigned a3,
                                        unsigned b0, unsigned b1) {
    asm volatile(
        "mma.sync.aligned.m16n8k16.row.col.f32.f16.f16.f32 "
        "{%0,%1,%2,%3},{%4,%5,%6,%7},{%8,%9},{%0,%1,%2,%3};\n"
        : "+f"(c0), "+f"(c1), "+f"(c2), "+f"(c3)
        : "r"(a0), "r"(a1), "r"(a2), "r"(a3), "r"(b0), "r"(b1));
}

__device__ __forceinline__ void ldsm_x4(unsigned& r0, unsigned& r1,
                                        unsigned& r2, unsigned& r3, unsigned addr) {
    asm volatile("ldmatrix.sync.aligned.m8n8.x4.shared.b16 {%0,%1,%2,%3}, [%4];\n"
                 : "=r"(r0), "=r"(r1), "=r"(r2), "=r"(r3) : "r"(addr));
}

__device__ __forceinline__ unsigned s2u(const void* p) {
    return (unsigned)__cvta_generic_to_shared(p);
}

__device__ __forceinline__ float bias_at(const float* Bs, int h, int i, int j) {
    int idx = ((i >> 3) - (j >> 3) + 7) * 15 + ((i & 7) - (j & 7) + 7);
    return Bs[idx * HEADS + h];
}

__global__ __launch_bounds__(NTHREADS, 1) void swin_win_attn_kernel(
    const float* __restrict__ x, const float* __restrict__ qkv_b,
    const float* __restrict__ proj_b, const float* __restrict__ bias_table,
    float* __restrict__ out)
{
    extern __shared__ char smem_raw[];
    __half* Wq = reinterpret_cast<__half*>(smem_raw);
    __half* Wp = Wq + H_WQ;
    __half* Xs = Wp + H_WP;      // input window; later attention output O
    __half* Qs = Xs + H_X;
    __half* Ks = Qs + H_Q;
    __half* Vt = Ks + H_K;
    float*  Bs = reinterpret_cast<float*>(Vt + H_V);
    float*  qb = Bs + 225*HEADS;
    float*  pb = qb + 384;

    const int tid = threadIdx.x, lane = tid & 31, wid = tid >> 5;
    const int g = lane >> 2, tg = lane & 3;

    // ldmatrix per-lane address offsets
    const int rA = ((lane >> 3) & 1) * 8 + (lane & 7);  // A: row within 16
    const int cA = (lane >> 4) * 8;                     // A: k-half
    const int rB = ((lane >> 4) & 1) * 8 + (lane & 7);  // B: n within 16 (two 8-blocks)
    const int cB = ((lane >> 3) & 1) * 8;               // B: k-half

    // ---- one-time per CTA: resident weights (vectorized) + biases ----
    {
        const uint4* src = reinterpret_cast<const uint4*>(g_qkvT);
        for (int i = tid; i < 384*16; i += NTHREADS) {
            int r = i >> 4, c = i & 15;
            *reinterpret_cast<uint4*>(Wq + r*WQP + c*8) = src[i];
        }
        const uint4* src2 = reinterpret_cast<const uint4*>(g_projT);
        for (int i = tid; i < 128*16; i += NTHREADS) {
            int r = i >> 4, c = i & 15;
            *reinterpret_cast<uint4*>(Wp + r*WPP + c*8) = src2[i];
        }
        for (int i = tid; i < 225*HEADS; i += NTHREADS) Bs[i] = bias_table[i];
        if (tid < 384) qb[tid] = qkv_b[tid];
        if (tid < 128) pb[tid] = proj_b[tid];
    }

    const float scale = 0.17677669529663687f;  // 32^-0.5

    // register-pipelined gather: this thread's 4 tokens x 8 halves
    unsigned hreg[8];
    const int c4 = lane * 4;            // column base (x4 floats)
    auto gather_regs = [&](int widx) {
        int bb = widx >> 12, wh = (widx >> 6) & 63, ww = widx & 63;
        #pragma unroll
        for (int k = 0; k < 4; ++k) {
            int t = wid + k * 16;       // token 0..63
            int i = t >> 3, j = t & 7;
            int gr = (wh*8 + i + SHIFTV) & 511;
            int gc = (ww*8 + j + SHIFTV) & 511;
            float4 v = *reinterpret_cast<const float4*>(
                x + (((size_t)bb*512 + gr)*512 + gc)*128 + c4);
            __half2 h0 = __floats2half2_rn(v.x, v.y);
            __half2 h1 = __floats2half2_rn(v.z, v.w);
            hreg[k*2]   = *reinterpret_cast<unsigned*>(&h0);
            hreg[k*2+1] = *reinterpret_cast<unsigned*>(&h1);
        }
    };
    auto store_regs = [&]() {
        #pragma unroll
        for (int k = 0; k < 4; ++k) {
            int t = wid + k * 16;
            *reinterpret_cast<unsigned*>(Xs + t*XP + c4)     = hreg[k*2];
            *reinterpret_cast<unsigned*>(Xs + t*XP + c4 + 2) = hreg[k*2+1];
        }
    };

    gather_regs(blockIdx.x * NW);

    for (int wi = 0; wi < NW; ++wi) {
        const int widx = blockIdx.x * NW + wi;
        const int b = widx >> 12, wh = (widx >> 6) & 63, ww = widx & 63;

        __syncthreads();   // Xs free (prev proj done); first iter: weights loaded
        store_regs();
        __syncthreads();

        // ---- QKV: [64x128]@[128x384]; warp = 32 rows x 48 cols ----
        {
            const int rh = wid & 1, cb = (wid >> 1) * 48;
            const unsigned aBase = s2u(Xs) + ((rh*32 + rA)*XP + cA) * 2;
            const unsigned bBase = s2u(Wq) + ((cb + rB)*WQP + cB) * 2;

            float c[2][6][4];
            #pragma unroll
            for (int mt = 0; mt < 2; ++mt)
                #pragma unroll
                for (int p = 0; p < 6; ++p)
                    c[mt][p][0] = c[mt][p][1] = c[mt][p][2] = c[mt][p][3] = 0.f;

            #pragma unroll
            for (int ks = 0; ks < 8; ++ks) {
                int k0 = ks * 16;
                unsigned a[2][4];
                ldsm_x4(a[0][0], a[0][1], a[0][2], a[0][3], aBase + k0*2);
                ldsm_x4(a[1][0], a[1][1], a[1][2], a[1][3], aBase + (16*XP + k0)*2);
                #pragma unroll
                for (int pp = 0; pp < 3; ++pp) {
                    unsigned bf[4];
                    ldsm_x4(bf[0], bf[1], bf[2], bf[3], bBase + (pp*16*WQP + k0)*2);
                    #pragma unroll
                    for (int mt = 0; mt < 2; ++mt) {
                        mma_f16(c[mt][2*pp][0], c[mt][2*pp][1], c[mt][2*pp][2], c[mt][2*pp][3],
                                a[mt][0], a[mt][1], a[mt][2], a[mt][3], bf[0], bf[1]);
                        mma_f16(c[mt][2*pp+1][0], c[mt][2*pp+1][1], c[mt][2*pp+1][2], c[mt][2*pp+1][3],
                                a[mt][0], a[mt][1], a[mt][2], a[mt][3], bf[2], bf[3]);
                    }
                }
            }
            // epilogue: route to Q / K / V(T) with bias
            #pragma unroll
            for (int p = 0; p < 6; ++p) {
                int col = cb + p*8 + 2*tg;
                int mat = col >> 7, head = (col >> 5) & 3, d = col & 31;
                float b0 = qb[col], b1 = qb[col + 1];
                #pragma unroll
                for (int mt = 0; mt < 2; ++mt) {
                    int row = rh*32 + mt*16 + g;
                    if (mat == 0) {
                        __half* Qh = Qs + head*64*QP;
                        *reinterpret_cast<__half2*>(Qh + row*QP + d) =
                            __floats2half2_rn(c[mt][p][0] + b0, c[mt][p][1] + b1);
                        *reinterpret_cast<__half2*>(Qh + (row+8)*QP + d) =
                            __floats2half2_rn(c[mt][p][2] + b0, c[mt][p][3] + b1);
                    } else if (mat == 1) {
                        __half* Kh = Ks + head*64*QP;
                        *reinterpret_cast<__half2*>(Kh + row*QP + d) =
                            __floats2half2_rn(c[mt][p][0] + b0, c[mt][p][1] + b1);
                        *reinterpret_cast<__half2*>(Kh + (row+8)*QP + d) =
                            __floats2half2_rn(c[mt][p][2] + b0, c[mt][p][3] + b1);
                    } else {
                        __half* Vh = Vt + head*32*VP;
                        Vh[d*VP + row]         = __float2half_rn(c[mt][p][0] + b0);
                        Vh[(d+1)*VP + row]     = __float2half_rn(c[mt][p][1] + b1);
                        Vh[d*VP + row + 8]     = __float2half_rn(c[mt][p][2] + b0);
                        Vh[(d+1)*VP + row + 8] = __float2half_rn(c[mt][p][3] + b1);
                    }
                }
            }
        }
        __syncthreads();

        // prefetch next window's input into registers (hidden behind attn+proj)
        if (wi + 1 < NW) gather_regs(widx + 1);

        // ---- attention: warp = (head, 16-row quarter); softmax in registers ----
        {
            const int h = wid >> 2, r0 = (wid & 3) * 16;
            const __half* Qh = Qs + h*64*QP;
            const __half* Kh = Ks + h*64*QP;
            const __half* Vh = Vt + h*32*VP;
            const unsigned qBase = s2u(Qh) + ((r0 + rA)*QP + cA) * 2;
            const unsigned kBase = s2u(Kh) + (rB*QP + cB) * 2;
            const unsigned vBase = s2u(Vh) + (rB*VP + cB) * 2;

            float s[8][4];
            #pragma unroll
            for (int nt = 0; nt < 8; ++nt)
                s[nt][0] = s[nt][1] = s[nt][2] = s[nt][3] = 0.f;

            #pragma unroll
            for (int kt = 0; kt < 2; ++kt) {
                int k0 = kt * 16;
                unsigned a[4];
                ldsm_x4(a[0], a[1], a[2], a[3], qBase + k0*2);
                #pragma unroll
                for (int ntp = 0; ntp < 4; ++ntp) {
                    unsigned bf[4];
                    ldsm_x4(bf[0], bf[1], bf[2], bf[3], kBase + (ntp*16*QP + k0)*2);
                    mma_f16(s[2*ntp][0], s[2*ntp][1], s[2*ntp][2], s[2*ntp][3],
                            a[0], a[1], a[2], a[3], bf[0], bf[1]);
                    mma_f16(s[2*ntp+1][0], s[2*ntp+1][1], s[2*ntp+1][2], s[2*ntp+1][3],
                            a[0], a[1], a[2], a[3], bf[2], bf[3]);
                }
            }

            // scale + bias + rowwise softmax (4 lanes per row via shfl)
            #pragma unroll
            for (int rr = 0; rr < 2; ++rr) {
                int row = r0 + g + rr*8;
                float m = -1e30f;
                #pragma unroll
                for (int nt = 0; nt < 8; ++nt) {
                    #pragma unroll
                    for (int q = 0; q < 2; ++q) {
                        int col = nt*8 + 2*tg + q;
                        float v = s[nt][rr*2+q] * scale + bias_at(Bs, h, row, col);
                        s[nt][rr*2+q] = v;
                        m = fmaxf(m, v);
                    }
                }
                m = fmaxf(m, __shfl_xor_sync(0xffffffffu, m, 1));
                m = fmaxf(m, __shfl_xor_sync(0xffffffffu, m, 2));
                float sum = 0.f;
                #pragma unroll
                for (int nt = 0; nt < 8; ++nt) {
                    #pragma unroll
                    for (int q = 0; q < 2; ++q) {
                        float e = __expf(s[nt][rr*2+q] - m);
                        s[nt][rr*2+q] = e;
                        sum += e;
                    }
                }
                sum += __shfl_xor_sync(0xffffffffu, sum, 1);
                sum += __shfl_xor_sync(0xffffffffu, sum, 2);
                float inv = 1.0f / sum;
                #pragma unroll
                for (int nt = 0; nt < 8; ++nt) {
                    s[nt][rr*2+0] *= inv;
                    s[nt][rr*2+1] *= inv;
                }
            }

            // repack probs (c-frag) as A-frags for PV
            unsigned af[4][4];
            #pragma unroll
            for (int kt = 0; kt < 4; ++kt) {
                __half2 h0 = __floats2half2_rn(s[2*kt][0],   s[2*kt][1]);
                __half2 h1 = __floats2half2_rn(s[2*kt][2],   s[2*kt][3]);
                __half2 h2 = __floats2half2_rn(s[2*kt+1][0], s[2*kt+1][1]);
                __half2 h3 = __floats2half2_rn(s[2*kt+1][2], s[2*kt+1][3]);
                af[kt][0] = *reinterpret_cast<unsigned*>(&h0);
                af[kt][1] = *reinterpret_cast<unsigned*>(&h1);
                af[kt][2] = *reinterpret_cast<unsigned*>(&h2);
                af[kt][3] = *reinterpret_cast<unsigned*>(&h3);
            }

            // O = P @ V  (B-frags from Vt via ldmatrix)
            float o[4][4];
            #pragma unroll
            for (int nt = 0; nt < 4; ++nt)
                o[nt][0] = o[nt][1] = o[nt][2] = o[nt][3] = 0.f;

            #pragma unroll
            for (int kt = 0; kt < 4; ++kt) {
                #pragma unroll
                for (int ntp = 0; ntp < 2; ++ntp) {
                    unsigned bf[4];
                    ldsm_x4(bf[0], bf[1], bf[2], bf[3], vBase + (ntp*16*VP + kt*16)*2);
                    mma_f16(o[2*ntp][0], o[2*ntp][1], o[2*ntp][2], o[2*ntp][3],
                            af[kt][0], af[kt][1], af[kt][2], af[kt][3], bf[0], bf[1]);
                    mma_f16(o[2*ntp+1][0], o[2*ntp+1][1], o[2*ntp+1][2], o[2*ntp+1][3],
                            af[kt][0], af[kt][1], af[kt][2], af[kt][3], bf[2], bf[3]);
                }
            }
            // write O into Xs (input dead now)
            #pragma unroll
            for (int nt = 0; nt < 4; ++nt) {
                int col = h*32 + nt*8 + 2*tg;
                int row = r0 + g;
                *reinterpret_cast<__half2*>(Xs + row*XP + col) =
                    __floats2half2_rn(o[nt][0], o[nt][1]);
                *reinterpret_cast<__half2*>(Xs + (row+8)*XP + col) =
                    __floats2half2_rn(o[nt][2], o[nt][3]);
            }
        }
        __syncthreads();

        // ---- proj: [64x128]@[128x128]; warp = 16 rows x 32 cols; scatter store ----
        {
            const int mh = wid >> 2, nq = wid & 3;
            const unsigned aBase = s2u(Xs) + ((mh*16 + rA)*XP + cA) * 2;
            const unsigned bBase = s2u(Wp) + ((nq*32 + rB)*WPP + cB) * 2;

            float c[4][4];
            #pragma unroll
            for (int nt = 0; nt < 4; ++nt)
                c[nt][0] = c[nt][1] = c[nt][2] = c[nt][3] = 0.f;

            #pragma unroll
            for (int ks = 0; ks < 8; ++ks) {
                int k0 = ks * 16;
                unsigned a[4];
                ldsm_x4(a[0], a[1], a[2], a[3], aBase + k0*2);
                #pragma unroll
                for (int ntp = 0; ntp < 2; ++ntp) {
                    unsigned bf[4];
                    ldsm_x4(bf[0], bf[1], bf[2], bf[3], bBase + (ntp*16*WPP + k0)*2);
                    mma_f16(c[2*ntp][0], c[2*ntp][1], c[2*ntp][2], c[2*ntp][3],
                            a[0], a[1], a[2], a[3], bf[0], bf[1]);
                    mma_f16(c[2*ntp+1][0], c[2*ntp+1][1], c[2*ntp+1][2], c[2*ntp+1][3],
                            a[0], a[1], a[2], a[3], bf[2], bf[3]);
                }
            }
            #pragma unroll
            for (int nt = 0; nt < 4; ++nt) {
                int col = nq*32 + nt*8 + 2*tg;
                float b0 = pb[col], b1 = pb[col + 1];
                #pragma unroll
                for (int rr = 0; rr < 2; ++rr) {
                    int t = mh*16 + g + rr*8;
                    int i = t >> 3, j = t & 7;
                    int gr = (wh*8 + i + SHIFTV) & 511;
                    int gc = (ww*8 + j + SHIFTV) & 511;
                    float2 st;
                    st.x = c[nt][rr*2+0] + b0;
                    st.y = c[nt][rr*2+1] + b1;
                    *reinterpret_cast<float2*>(
                        out + (((size_t)b*512 + gr)*512 + gc)*128 + col) = st;
                }
            }
        }
    }
}

extern "C" void kernel_launch(void* const* d_in, const int* in_sizes, int n_in,
                              void* d_out, int out_size)
{
    const float* x          = (const float*)d_in[0];
    const float* qkv_w      = (const float*)d_in[1];
    const float* qkv_b      = (const float*)d_in[2];
    const float* proj_w     = (const float*)d_in[3];
    const float* proj_b     = (const float*)d_in[4];
    const float* bias_table = (const float*)d_in[5];
    float* out = (float*)d_out;

    prep_qkv<<<(384*128 + 255)/256, 256>>>(qkv_w);
    prep_proj<<<(128*128 + 255)/256, 256>>>(proj_w);

    cudaFuncSetAttribute(swin_win_attn_kernel,
                         cudaFuncAttributeMaxDynamicSharedMemorySize, SMEM_BYTES);
    swin_win_attn_kernel<<<16384/NW, NTHREADS, SMEM_BYTES>>>(
        x, qkv_b, proj_b, bias_table, out);
}